// round 2
// baseline (speedup 1.0000x reference)
#include <cuda_runtime.h>
#include <math.h>

#define HH 64
#define WW 64
#define NUM_POS 48
#define CHAN_PER_POS 8
#define CC 384
#define BB 32
#define SM_W 68           // padded smem row stride (floats), multiple of 4 -> 16B-aligned rows
#define TILE_ROWS 66      // displaced rows [-1, 64]
#define TILE_COLS 66

__global__ __launch_bounds__(256, 8)
void displace_gauss_kernel(const float* __restrict__ inp,
                           const float* __restrict__ offset,
                           float* __restrict__ out)
{
    __shared__ float tile[TILE_ROWS * SM_W];

    const int c = blockIdx.x;          // channel 0..383
    const int b = blockIdx.y;          // batch 0..31
    const int pos = c >> 3;            // c / CHAN_PER_POS

    // --- offsets & per-position Gaussian weights (registers, per-thread) ---
    const float offx = offset[pos * 2 + 0];
    const float offy = offset[pos * 2 + 1];
    const float rx = rintf(offx);      // matches jnp.round (no .5 ties by construction)
    const float ry = rintf(offy);
    const int ox = (int)rx;
    const int oy = (int)ry;
    const float fx = offx - rx;
    const float fy = offy - ry;

    float w[9];
    float wsum = 0.f;
    #pragma unroll
    for (int ky = 0; ky < 3; ky++) {
        #pragma unroll
        for (int kx = 0; kx < 3; kx++) {
            const float dx = (float)(kx - 1) + fx;
            const float dy = (float)(ky - 1) + fy;
            const float v = expf(-2.0f * (dx * dx + dy * dy));   // sigma = 0.5
            w[ky * 3 + kx] = v;
            wsum += v;
        }
    }
    const float winv = 1.0f / wsum;
    #pragma unroll
    for (int i = 0; i < 9; i++) w[i] *= winv;

    // --- stage displaced + masked tile into smem (66x66 incl. conv halo) ---
    const float* __restrict__ src = inp + ((size_t)b * CC + c) * (HH * WW);
    for (int i = threadIdx.x; i < TILE_ROWS * TILE_COLS; i += 256) {
        const int yy = i / TILE_COLS - 1;   // displaced-plane row in [-1, 64]
        const int xx = i % TILE_COLS - 1;   // displaced-plane col in [-1, 64]
        const int sy = yy - oy;             // source row
        const int sx = xx - ox;             // source col
        float v = 0.0f;
        if ((unsigned)yy < HH && (unsigned)xx < WW &&
            (unsigned)sy < HH && (unsigned)sx < WW) {
            v = __ldg(&src[sy * WW + sx]);
        }
        tile[(yy + 1) * SM_W + (xx + 1)] = v;
    }
    __syncthreads();

    // --- 3x3 conv: each thread produces 4 consecutive pixels per iteration ---
    float* __restrict__ dst = out + ((size_t)b * CC + c) * (HH * WW);
    #pragma unroll
    for (int it = 0; it < 4; it++) {
        const int gid = it * 256 + threadIdx.x;   // float4 index in plane
        const int y  = gid >> 4;                  // 16 float4 per row
        const int x4 = (gid & 15) << 2;           // starting x (mult of 4)

        float a0 = 0.f, a1 = 0.f, a2 = 0.f, a3 = 0.f;
        #pragma unroll
        for (int ky = 0; ky < 3; ky++) {
            const float* r = &tile[(y + ky) * SM_W + x4];
            const float4 va = *(const float4*)(r);       // cols x4 .. x4+3
            const float4 vb = *(const float4*)(r + 4);   // cols x4+4 .. x4+7 (use .x,.y)
            const float w0 = w[ky * 3 + 0];
            const float w1 = w[ky * 3 + 1];
            const float w2 = w[ky * 3 + 2];
            a0 = fmaf(w0, va.x, fmaf(w1, va.y, fmaf(w2, va.z, a0)));
            a1 = fmaf(w0, va.y, fmaf(w1, va.z, fmaf(w2, va.w, a1)));
            a2 = fmaf(w0, va.z, fmaf(w1, va.w, fmaf(w2, vb.x, a2)));
            a3 = fmaf(w0, va.w, fmaf(w1, vb.x, fmaf(w2, vb.y, a3)));
        }
        *(float4*)&dst[y * WW + x4] = make_float4(a0, a1, a2, a3);
    }
}

extern "C" void kernel_launch(void* const* d_in, const int* in_sizes, int n_in,
                              void* d_out, int out_size)
{
    const float* inp    = (const float*)d_in[0];   // (32, 384, 64, 64) fp32
    const float* offset = (const float*)d_in[1];   // (48, 2) fp32
    float* out          = (float*)d_out;           // (32, 384, 64, 64) fp32

    dim3 grid(CC, BB);   // (384, 32) -> one CTA per (b, c) plane
    displace_gauss_kernel<<<grid, 256>>>(inp, offset, out);
}